// round 7
// baseline (speedup 1.0000x reference)
#include <cuda_runtime.h>
#include <math_constants.h>
#include <cstdint>

#define BB    4
#define NN    2048
#define DIMC  768
#define HEADS 12
#define HD    64
#define MTOK  (BB * NN)   /* 8192 tokens */

// Scratch (allocation-free rule: __device__ globals)
__device__ float g_qkv[(size_t)MTOK * 3 * DIMC];   // [8192, 2304]
__device__ float g_att[(size_t)MTOK * DIMC];       // [8192, 768]

// ---------------------------------------------------------------------------
// tf32 helpers (sm_80+ PTX only — NO 'a'-gated instructions)
// ---------------------------------------------------------------------------
__device__ __forceinline__ uint32_t f2tf(float x) {
    uint32_t r;
    asm("cvt.rna.tf32.f32 %0, %1;" : "=r"(r) : "f"(x));
    return r;
}

// D += A @ B ; m16n8k8 tf32, fp32 accumulate.
// A frag: a0=(g,t) a1=(g+8,t) a2=(g,t+4) a3=(g+8,t+4); g=lane>>2, t=lane&3
// B frag: b0=(k=t, n=g) b1=(k=t+4, n=g)
// C frag: c0=(g,2t) c1=(g,2t+1) c2=(g+8,2t) c3=(g+8,2t+1)
__device__ __forceinline__ void mma_tf32(float* d, const uint32_t* a, const uint32_t* b) {
    asm volatile(
        "mma.sync.aligned.m16n8k8.row.col.f32.tf32.tf32.f32 "
        "{%0,%1,%2,%3}, {%4,%5,%6,%7}, {%8,%9}, {%0,%1,%2,%3};"
        : "+f"(d[0]), "+f"(d[1]), "+f"(d[2]), "+f"(d[3])
        : "r"(a[0]), "r"(a[1]), "r"(a[2]), "r"(a[3]), "r"(b[0]), "r"(b[1]));
}

// Within-8 column permutation so that (c, c+4) land adjacent -> LDS.64 frags.
// p(j) = 2*(j&3) + (j>>2), applied per 8-wide k-block.
__device__ __forceinline__ int pcol(int c) {
    return (c & ~7) + ((c & 3) << 1) + ((c >> 2) & 1);
}

// ===========================================================================
// GEMM: C[M,N] = A[M,K] @ B[K,N] + bias[N]   (tf32 mma.sync)
// 128x128 tile, BK=32, 256 threads (8 warps, 4x2 layout, warp tile 32x64).
// Double-buffered smem; permuted layout; LDS.64 fragment loads.
// Requires M%128==0, N%128==0, K%32==0 (true for all shapes here).
// ===========================================================================
#define GBK  32
#define GSTR 36                       // 32 + 4 pad (words)
#define GEMM_SMEM (18432 * 4)         // 2 bufs * (A 128*36 + B 128*36) words

__global__ __launch_bounds__(256, 1)
void gemm_mma(const float* __restrict__ A, const float* __restrict__ B,
              const float* __restrict__ bias, float* __restrict__ C,
              int N, int K)
{
    extern __shared__ uint32_t dsm[];
    const int tid  = threadIdx.x;
    const int lane = tid & 31, wid = tid >> 5;
    const int g = lane >> 2, t = lane & 3;
    const int bm = blockIdx.y * 128, bn = blockIdx.x * 128;
    const int wm = (wid & 3) * 32, wn = (wid >> 2) * 64;

    // LDG mapping
    const int ar = tid >> 1, ah = (tid & 1) * 16;   // A: row ar, cols ah..ah+15
    const int bk = tid >> 3, bj = tid & 7;          // B: row bk, float4 slots bj+8i
    const float* Aq = A + (size_t)(bm + ar) * K + ah;
    const float* Bq = B + (size_t)bk * N + bn + bj * 4;

    float acc[2][8][4];
#pragma unroll
    for (int mt = 0; mt < 2; mt++)
#pragma unroll
        for (int nt = 0; nt < 8; nt++)
#pragma unroll
            for (int r = 0; r < 4; r++) acc[mt][nt][r] = 0.0f;

    float4 a_ld[4], b_ld[4];

#define GEMM_LDG(kt) do {                                                     \
    _Pragma("unroll")                                                         \
    for (int i = 0; i < 4; i++) {                                             \
        a_ld[i] = *(const float4*)(Aq + (size_t)(kt) * GBK + i * 4);          \
        b_ld[i] = *(const float4*)(Bq + (size_t)(kt) * GBK * N + 32 * i);     \
    } } while (0)

#define GEMM_STS(buf) do {                                                    \
    uint32_t* as_ = dsm + (buf) * 9216;                                       \
    uint32_t* bs_ = as_ + 4608;                                               \
    _Pragma("unroll")                                                         \
    for (int i = 0; i < 4; i++) {                                             \
        const float av_[4] = {a_ld[i].x, a_ld[i].y, a_ld[i].z, a_ld[i].w};    \
        const float bv_[4] = {b_ld[i].x, b_ld[i].y, b_ld[i].z, b_ld[i].w};    \
        const int n0_ = (bj + 8 * i) * 4;                                     \
        _Pragma("unroll")                                                     \
        for (int e = 0; e < 4; e++) {                                         \
            as_[ar * GSTR + pcol(ah + i * 4 + e)] = f2tf(av_[e]);             \
            bs_[(n0_ + e) * GSTR + pcol(bk)]      = f2tf(bv_[e]);             \
        }                                                                     \
    } } while (0)

    const int NT = K / GBK;
    GEMM_LDG(0);
    GEMM_STS(0);

    for (int kt = 0; kt < NT; kt++) {
        __syncthreads();
        if (kt + 1 < NT) GEMM_LDG(kt + 1);

        const uint32_t* as = dsm + (kt & 1) * 9216;
        const uint32_t* bs = as + 4608;
#pragma unroll
        for (int ks = 0; ks < 4; ks++) {
            uint32_t af[2][4], bf[8][2];
#pragma unroll
            for (int mt = 0; mt < 2; mt++) {
                const int r0 = wm + mt * 16 + g;
                uint2 lo = *(const uint2*)&as[r0 * GSTR + ks * 8 + 2 * t];
                uint2 hi = *(const uint2*)&as[(r0 + 8) * GSTR + ks * 8 + 2 * t];
                af[mt][0] = lo.x; af[mt][1] = hi.x; af[mt][2] = lo.y; af[mt][3] = hi.y;
            }
#pragma unroll
            for (int nt = 0; nt < 8; nt++) {
                uint2 bb = *(const uint2*)&bs[(wn + nt * 8 + g) * GSTR + ks * 8 + 2 * t];
                bf[nt][0] = bb.x; bf[nt][1] = bb.y;
            }
#pragma unroll
            for (int mt = 0; mt < 2; mt++)
#pragma unroll
                for (int nt = 0; nt < 8; nt++)
                    mma_tf32(acc[mt][nt], af[mt], bf[nt]);
        }
        if (kt + 1 < NT) GEMM_STS((kt + 1) & 1);
    }

    // epilogue: bias + float2 stores
#pragma unroll
    for (int mt = 0; mt < 2; mt++)
#pragma unroll
        for (int rr = 0; rr < 2; rr++) {
            const int row = bm + wm + mt * 16 + g + rr * 8;
            float* Cr = C + (size_t)row * N;
#pragma unroll
            for (int nt = 0; nt < 8; nt++) {
                const int col = bn + wn + nt * 8 + 2 * t;
                float2 bb = *(const float2*)(bias + col);
                float2 o;
                o.x = acc[mt][nt][rr * 2 + 0] + bb.x;
                o.y = acc[mt][nt][rr * 2 + 1] + bb.y;
                *(float2*)(Cr + col) = o;
            }
        }
#undef GEMM_LDG
#undef GEMM_STS
}

// ===========================================================================
// Flash attention, tf32 mma for both S=Q@K^T and O+=P@V. head_dim=64.
// Block = (b, h, 128 q-rows); 8 warps, warp = 16 q-rows (one m16 tile).
// K-tile = 64 keys/iter. Online softmax in C-fragment layout (quad shfl).
// P converted C-frag -> A-frag via per-warp-private smem (syncwarp only).
// smem words: Qs 9216 | Ks 4608 | Vs 4608 | Ps 9216  (stride 72)
// ===========================================================================
#define ASTRD 72
#define ATT_SMEM (27648 * 4)

__global__ __launch_bounds__(256, 2)
void attn_mma(const float* __restrict__ qkv, float* __restrict__ outp)
{
    extern __shared__ uint32_t dsm[];
    uint32_t* Qs = dsm;
    uint32_t* Ks = dsm + 9216;
    uint32_t* Vs = dsm + 13824;
    uint32_t* Ps = dsm + 18432;

    const int tid = threadIdx.x, lane = tid & 31, w = tid >> 5;
    const int g = lane >> 2, t = lane & 3;
    const int qt = blockIdx.x & 15;
    const int h  = (blockIdx.x >> 4) % HEADS;
    const int b  = blockIdx.x / (16 * HEADS);
    const int q0 = qt * 128;

    // ---- Q fill: scaled by d^-0.5, tf32, permuted layout ----
    {
        const int row = tid >> 1, half = (tid & 1) * 32;
        const float* qp = qkv + (size_t)(b * NN + q0 + row) * (3 * DIMC) + h * HD + half;
#pragma unroll
        for (int i = 0; i < 8; i++) {
            float4 v = *(const float4*)(qp + i * 4);
            const float vv[4] = {v.x, v.y, v.z, v.w};
#pragma unroll
            for (int e = 0; e < 4; e++)
                Qs[row * ASTRD + pcol(half + i * 4 + e)] = f2tf(vv[e] * 0.125f);
        }
    }

    float o[8][4];
#pragma unroll
    for (int nt = 0; nt < 8; nt++)
#pragma unroll
        for (int r = 0; r < 4; r++) o[nt][r] = 0.0f;
    float m0 = -CUDART_INF_F, m1 = -CUDART_INF_F, l0 = 0.0f, l1 = 0.0f;

    const int r0 = 16 * w + g;
    const int key = tid >> 2, c4 = tid & 3;
    const float* kvbase = qkv + (size_t)(b * NN + key) * (3 * DIMC) + h * HD;

    for (int kt = 0; kt < NN / 64; kt++) {
        // prefetch K/V tile (overlaps previous iter's compute)
        float4 kf[4], vf[4];
        const float* kp = kvbase + (size_t)(kt * 64) * (3 * DIMC) + DIMC;
        const float* vp = kp + DIMC;
#pragma unroll
        for (int i = 0; i < 4; i++) {
            kf[i] = *(const float4*)(kp + (c4 + 4 * i) * 4);
            vf[i] = *(const float4*)(vp + (c4 + 4 * i) * 4);
        }
        __syncthreads();   // previous iteration's Ks/Vs reads complete
#pragma unroll
        for (int i = 0; i < 4; i++) {
            const float kv_[4] = {kf[i].x, kf[i].y, kf[i].z, kf[i].w};
            const float vv_[4] = {vf[i].x, vf[i].y, vf[i].z, vf[i].w};
#pragma unroll
            for (int e = 0; e < 4; e++) {
                const int d = (c4 + 4 * i) * 4 + e;
                Ks[key * ASTRD + pcol(d)] = f2tf(kv_[e]);      // K: [key][d']
                Vs[d * ASTRD + pcol(key)] = f2tf(vv_[e]);      // V^T: [d][key']
            }
        }
        __syncthreads();

        // ---- S = Q @ K^T (n = keys, k = d) ----
        float s[8][4];
#pragma unroll
        for (int nt = 0; nt < 8; nt++)
#pragma unroll
            for (int r = 0; r < 4; r++) s[nt][r] = 0.0f;

#pragma unroll
        for (int ks = 0; ks < 8; ks++) {
            uint2 alo = *(const uint2*)&Qs[r0 * ASTRD + ks * 8 + 2 * t];
            uint2 ahi = *(const uint2*)&Qs[(r0 + 8) * ASTRD + ks * 8 + 2 * t];
            uint32_t a[4] = {alo.x, ahi.x, alo.y, ahi.y};
#pragma unroll
            for (int nt = 0; nt < 8; nt++) {
                uint2 bb = *(const uint2*)&Ks[(nt * 8 + g) * ASTRD + ks * 8 + 2 * t];
                uint32_t bf2[2] = {bb.x, bb.y};
                mma_tf32(s[nt], a, bf2);
            }
        }

        // ---- online softmax (rows g and g+8; quad = same row) ----
        float mx0 = -CUDART_INF_F, mx1 = -CUDART_INF_F;
#pragma unroll
        for (int nt = 0; nt < 8; nt++) {
            mx0 = fmaxf(mx0, fmaxf(s[nt][0], s[nt][1]));
            mx1 = fmaxf(mx1, fmaxf(s[nt][2], s[nt][3]));
        }
        mx0 = fmaxf(mx0, __shfl_xor_sync(0xffffffffu, mx0, 1));
        mx0 = fmaxf(mx0, __shfl_xor_sync(0xffffffffu, mx0, 2));
        mx1 = fmaxf(mx1, __shfl_xor_sync(0xffffffffu, mx1, 1));
        mx1 = fmaxf(mx1, __shfl_xor_sync(0xffffffffu, mx1, 2));
        const float nm0 = fmaxf(m0, mx0), nm1 = fmaxf(m1, mx1);
        const float cr0 = __expf(m0 - nm0), cr1 = __expf(m1 - nm1);
        float rs0 = 0.0f, rs1 = 0.0f;
#pragma unroll
        for (int nt = 0; nt < 8; nt++) {
            s[nt][0] = __expf(s[nt][0] - nm0);
            s[nt][1] = __expf(s[nt][1] - nm0);
            s[nt][2] = __expf(s[nt][2] - nm1);
            s[nt][3] = __expf(s[nt][3] - nm1);
            rs0 += s[nt][0] + s[nt][1];
            rs1 += s[nt][2] + s[nt][3];
        }
        rs0 += __shfl_xor_sync(0xffffffffu, rs0, 1);
        rs0 += __shfl_xor_sync(0xffffffffu, rs0, 2);
        rs1 += __shfl_xor_sync(0xffffffffu, rs1, 1);
        rs1 += __shfl_xor_sync(0xffffffffu, rs1, 2);
        l0 = l0 * cr0 + rs0;  m0 = nm0;
        l1 = l1 * cr1 + rs1;  m1 = nm1;
#pragma unroll
        for (int nt = 0; nt < 8; nt++) {
            o[nt][0] *= cr0; o[nt][1] *= cr0;
            o[nt][2] *= cr1; o[nt][3] *= cr1;
        }

        // ---- P: C-frag -> smem (per-warp private rows) ----
#pragma unroll
        for (int nt = 0; nt < 8; nt++) {
            const int j0 = nt * 8 + 2 * t;
            Ps[r0 * ASTRD + pcol(j0)]           = f2tf(s[nt][0]);
            Ps[r0 * ASTRD + pcol(j0 + 1)]       = f2tf(s[nt][1]);
            Ps[(r0 + 8) * ASTRD + pcol(j0)]     = f2tf(s[nt][2]);
            Ps[(r0 + 8) * ASTRD + pcol(j0 + 1)] = f2tf(s[nt][3]);
        }
        __syncwarp();

        // ---- O += P @ V (n = d, k = keys) ----
#pragma unroll
        for (int ks = 0; ks < 8; ks++) {
            uint2 plo = *(const uint2*)&Ps[r0 * ASTRD + ks * 8 + 2 * t];
            uint2 phi = *(const uint2*)&Ps[(r0 + 8) * ASTRD + ks * 8 + 2 * t];
            uint32_t a[4] = {plo.x, phi.x, plo.y, phi.y};
#pragma unroll
            for (int nt = 0; nt < 8; nt++) {
                uint2 bb = *(const uint2*)&Vs[(nt * 8 + g) * ASTRD + ks * 8 + 2 * t];
                uint32_t bf2[2] = {bb.x, bb.y};
                mma_tf32(o[nt], a, bf2);
            }
        }
        __syncwarp();
    }

    // ---- epilogue: normalize, store to [B*N, 768] ----
    const float inv0 = 1.0f / l0, inv1 = 1.0f / l1;
    const int grow = b * NN + q0 + 16 * w + g;
    float* or0 = outp + (size_t)grow * DIMC + h * HD;
    float* or1 = outp + (size_t)(grow + 8) * DIMC + h * HD;
#pragma unroll
    for (int nt = 0; nt < 8; nt++) {
        const int col = nt * 8 + 2 * t;
        float2 v0; v0.x = o[nt][0] * inv0; v0.y = o[nt][1] * inv0;
        float2 v1; v1.x = o[nt][2] * inv1; v1.y = o[nt][3] * inv1;
        *(float2*)(or0 + col) = v0;
        *(float2*)(or1 + col) = v1;
    }
}

// ---------------------------------------------------------------------------
extern "C" void kernel_launch(void* const* d_in, const int* in_sizes, int n_in,
                              void* d_out, int out_size)
{
    const float* x      = (const float*)d_in[0];
    const float* w_qkv  = (const float*)d_in[1];
    const float* b_qkv  = (const float*)d_in[2];
    const float* w_proj = (const float*)d_in[3];
    const float* b_proj = (const float*)d_in[4];
    float* out = (float*)d_out;

    float *qkv_s = nullptr, *att_s = nullptr;
    cudaGetSymbolAddress((void**)&qkv_s, g_qkv);
    cudaGetSymbolAddress((void**)&att_s, g_att);

    cudaFuncSetAttribute(gemm_mma, cudaFuncAttributeMaxDynamicSharedMemorySize, GEMM_SMEM);
    cudaFuncSetAttribute(attn_mma, cudaFuncAttributeMaxDynamicSharedMemorySize, ATT_SMEM);

    // 1) QKV GEMM: [8192,768] @ [768,2304] + bias
    {
        dim3 grid((3 * DIMC) / 128, MTOK / 128);
        gemm_mma<<<grid, 256, GEMM_SMEM>>>(x, w_qkv, b_qkv, qkv_s, 3 * DIMC, DIMC);
    }

    // 2) Flash attention (tf32 mma): 4*12*16 = 768 blocks
    attn_mma<<<BB * HEADS * 16, 256, ATT_SMEM>>>(qkv_s, att_s);

    // 3) Projection GEMM: [8192,768] @ [768,768] + bias
    {
        dim3 grid(DIMC / 128, MTOK / 128);
        gemm_mma<<<grid, 256, GEMM_SMEM>>>(att_s, w_proj, b_proj, out, DIMC, DIMC);
    }
}

// round 8
// speedup vs baseline: 1.0022x; 1.0022x over previous
#include <cuda_runtime.h>
#include <math_constants.h>
#include <cstdint>

#define BB    4
#define NN    2048
#define DIMC  768
#define HEADS 12
#define HD    64
#define MTOK  (BB * NN)   /* 8192 tokens */

// Scratch (allocation-free rule: __device__ globals)
__device__ float g_qkv[(size_t)MTOK * 3 * DIMC];   // [8192, 2304]
__device__ float g_att[(size_t)MTOK * DIMC];       // [8192, 768]

// ---------------------------------------------------------------------------
// tf32 helpers (sm_80+ PTX only — NO 'a'-gated instructions)
// ---------------------------------------------------------------------------
__device__ __forceinline__ uint32_t f2tf(float x) {
    uint32_t r;
    asm("cvt.rna.tf32.f32 %0, %1;" : "=r"(r) : "f"(x));
    return r;
}

// D += A @ B ; m16n8k8 tf32, fp32 accumulate.
// A frag: a0=(g,t) a1=(g+8,t) a2=(g,t+4) a3=(g+8,t+4); g=lane>>2, t=lane&3
// B frag: b0=(k=t, n=g) b1=(k=t+4, n=g)
// C frag: c0=(g,2t) c1=(g,2t+1) c2=(g+8,2t) c3=(g+8,2t+1)
__device__ __forceinline__ void mma_tf32(float* d, const uint32_t* a, const uint32_t* b) {
    asm volatile(
        "mma.sync.aligned.m16n8k8.row.col.f32.tf32.tf32.f32 "
        "{%0,%1,%2,%3}, {%4,%5,%6,%7}, {%8,%9}, {%0,%1,%2,%3};"
        : "+f"(d[0]), "+f"(d[1]), "+f"(d[2]), "+f"(d[3])
        : "r"(a[0]), "r"(a[1]), "r"(a[2]), "r"(a[3]), "r"(b[0]), "r"(b[1]));
}

// Within-8 column permutation so that (c, c+4) land adjacent -> LDS.64 frags.
// p(j) = 2*(j&3) + (j>>2), applied per 8-wide k-block.
__device__ __forceinline__ int pcol(int c) {
    return (c & ~7) + ((c & 3) << 1) + ((c >> 2) & 1);
}

// ===========================================================================
// GEMM: C[M,N] = A[M,K] @ B[K,N] + bias[N]   (tf32 mma.sync)
// 128x128 tile, BK=32, 256 threads (8 warps, 4x2 layout, warp tile 32x64).
// Double-buffered smem; permuted layout; LDS.64 fragment loads.
// Requires M%128==0, N%128==0, K%32==0 (true for all shapes here).
// ===========================================================================
#define GBK  32
#define GSTR 36                       // 32 + 4 pad (words)
#define GEMM_SMEM (18432 * 4)         // 2 bufs * (A 128*36 + B 128*36) words

__global__ __launch_bounds__(256, 1)
void gemm_mma(const float* __restrict__ A, const float* __restrict__ B,
              const float* __restrict__ bias, float* __restrict__ C,
              int N, int K)
{
    extern __shared__ uint32_t dsm[];
    const int tid  = threadIdx.x;
    const int lane = tid & 31, wid = tid >> 5;
    const int g = lane >> 2, t = lane & 3;
    const int bm = blockIdx.y * 128, bn = blockIdx.x * 128;
    const int wm = (wid & 3) * 32, wn = (wid >> 2) * 64;

    // LDG mapping
    const int ar = tid >> 1, ah = (tid & 1) * 16;   // A: row ar, cols ah..ah+15
    const int bk = tid >> 3, bj = tid & 7;          // B: row bk, float4 slots bj+8i
    const float* Aq = A + (size_t)(bm + ar) * K + ah;
    const float* Bq = B + (size_t)bk * N + bn + bj * 4;

    float acc[2][8][4];
#pragma unroll
    for (int mt = 0; mt < 2; mt++)
#pragma unroll
        for (int nt = 0; nt < 8; nt++)
#pragma unroll
            for (int r = 0; r < 4; r++) acc[mt][nt][r] = 0.0f;

    float4 a_ld[4], b_ld[4];

#define GEMM_LDG(kt) do {                                                     \
    _Pragma("unroll")                                                         \
    for (int i = 0; i < 4; i++) {                                             \
        a_ld[i] = *(const float4*)(Aq + (size_t)(kt) * GBK + i * 4);          \
        b_ld[i] = *(const float4*)(Bq + (size_t)(kt) * GBK * N + 32 * i);     \
    } } while (0)

#define GEMM_STS(buf) do {                                                    \
    uint32_t* as_ = dsm + (buf) * 9216;                                       \
    uint32_t* bs_ = as_ + 4608;                                               \
    _Pragma("unroll")                                                         \
    for (int i = 0; i < 4; i++) {                                             \
        const float av_[4] = {a_ld[i].x, a_ld[i].y, a_ld[i].z, a_ld[i].w};    \
        const float bv_[4] = {b_ld[i].x, b_ld[i].y, b_ld[i].z, b_ld[i].w};    \
        const int n0_ = (bj + 8 * i) * 4;                                     \
        _Pragma("unroll")                                                     \
        for (int e = 0; e < 4; e++) {                                         \
            as_[ar * GSTR + pcol(ah + i * 4 + e)] = f2tf(av_[e]);             \
            bs_[(n0_ + e) * GSTR + pcol(bk)]      = f2tf(bv_[e]);             \
        }                                                                     \
    } } while (0)

    const int NT = K / GBK;
    GEMM_LDG(0);
    GEMM_STS(0);

    for (int kt = 0; kt < NT; kt++) {
        __syncthreads();
        if (kt + 1 < NT) GEMM_LDG(kt + 1);

        const uint32_t* as = dsm + (kt & 1) * 9216;
        const uint32_t* bs = as + 4608;
#pragma unroll
        for (int ks = 0; ks < 4; ks++) {
            uint32_t af[2][4], bf[8][2];
#pragma unroll
            for (int mt = 0; mt < 2; mt++) {
                const int r0 = wm + mt * 16 + g;
                uint2 lo = *(const uint2*)&as[r0 * GSTR + ks * 8 + 2 * t];
                uint2 hi = *(const uint2*)&as[(r0 + 8) * GSTR + ks * 8 + 2 * t];
                af[mt][0] = lo.x; af[mt][1] = hi.x; af[mt][2] = lo.y; af[mt][3] = hi.y;
            }
#pragma unroll
            for (int nt = 0; nt < 8; nt++) {
                uint2 bb = *(const uint2*)&bs[(wn + nt * 8 + g) * GSTR + ks * 8 + 2 * t];
                bf[nt][0] = bb.x; bf[nt][1] = bb.y;
            }
#pragma unroll
            for (int mt = 0; mt < 2; mt++)
#pragma unroll
                for (int nt = 0; nt < 8; nt++)
                    mma_tf32(acc[mt][nt], af[mt], bf[nt]);
        }
        if (kt + 1 < NT) GEMM_STS((kt + 1) & 1);
    }

    // epilogue: bias + float2 stores
#pragma unroll
    for (int mt = 0; mt < 2; mt++)
#pragma unroll
        for (int rr = 0; rr < 2; rr++) {
            const int row = bm + wm + mt * 16 + g + rr * 8;
            float* Cr = C + (size_t)row * N;
#pragma unroll
            for (int nt = 0; nt < 8; nt++) {
                const int col = bn + wn + nt * 8 + 2 * t;
                float2 bb = *(const float2*)(bias + col);
                float2 o;
                o.x = acc[mt][nt][rr * 2 + 0] + bb.x;
                o.y = acc[mt][nt][rr * 2 + 1] + bb.y;
                *(float2*)(Cr + col) = o;
            }
        }
#undef GEMM_LDG
#undef GEMM_STS
}

// ===========================================================================
// Flash attention, tf32 mma for both S=Q@K^T and O+=P@V. head_dim=64.
// Block = (b, h, 128 q-rows); 8 warps, warp = 16 q-rows (one m16 tile).
// K-tile = 64 keys/iter. Online softmax in C-fragment layout (quad shfl).
// P converted C-frag -> A-frag via per-warp-private smem (syncwarp only).
// smem words: Qs 9216 | Ks 4608 | Vs 4608 | Ps 9216  (stride 72)
// ===========================================================================
#define ASTRD 72
#define ATT_SMEM (27648 * 4)

__global__ __launch_bounds__(256, 2)
void attn_mma(const float* __restrict__ qkv, float* __restrict__ outp)
{
    extern __shared__ uint32_t dsm[];
    uint32_t* Qs = dsm;
    uint32_t* Ks = dsm + 9216;
    uint32_t* Vs = dsm + 13824;
    uint32_t* Ps = dsm + 18432;

    const int tid = threadIdx.x, lane = tid & 31, w = tid >> 5;
    const int g = lane >> 2, t = lane & 3;
    const int qt = blockIdx.x & 15;
    const int h  = (blockIdx.x >> 4) % HEADS;
    const int b  = blockIdx.x / (16 * HEADS);
    const int q0 = qt * 128;

    // ---- Q fill: scaled by d^-0.5, tf32, permuted layout ----
    {
        const int row = tid >> 1, half = (tid & 1) * 32;
        const float* qp = qkv + (size_t)(b * NN + q0 + row) * (3 * DIMC) + h * HD + half;
#pragma unroll
        for (int i = 0; i < 8; i++) {
            float4 v = *(const float4*)(qp + i * 4);
            const float vv[4] = {v.x, v.y, v.z, v.w};
#pragma unroll
            for (int e = 0; e < 4; e++)
                Qs[row * ASTRD + pcol(half + i * 4 + e)] = f2tf(vv[e] * 0.125f);
        }
    }

    float o[8][4];
#pragma unroll
    for (int nt = 0; nt < 8; nt++)
#pragma unroll
        for (int r = 0; r < 4; r++) o[nt][r] = 0.0f;
    float m0 = -CUDART_INF_F, m1 = -CUDART_INF_F, l0 = 0.0f, l1 = 0.0f;

    const int r0 = 16 * w + g;
    const int key = tid >> 2, c4 = tid & 3;
    const float* kvbase = qkv + (size_t)(b * NN + key) * (3 * DIMC) + h * HD;

    for (int kt = 0; kt < NN / 64; kt++) {
        // prefetch K/V tile (overlaps previous iter's compute)
        float4 kf[4], vf[4];
        const float* kp = kvbase + (size_t)(kt * 64) * (3 * DIMC) + DIMC;
        const float* vp = kp + DIMC;
#pragma unroll
        for (int i = 0; i < 4; i++) {
            kf[i] = *(const float4*)(kp + (c4 + 4 * i) * 4);
            vf[i] = *(const float4*)(vp + (c4 + 4 * i) * 4);
        }
        __syncthreads();   // previous iteration's Ks/Vs reads complete
#pragma unroll
        for (int i = 0; i < 4; i++) {
            const float kv_[4] = {kf[i].x, kf[i].y, kf[i].z, kf[i].w};
            const float vv_[4] = {vf[i].x, vf[i].y, vf[i].z, vf[i].w};
#pragma unroll
            for (int e = 0; e < 4; e++) {
                const int d = (c4 + 4 * i) * 4 + e;
                Ks[key * ASTRD + pcol(d)] = f2tf(kv_[e]);      // K: [key][d']
                Vs[d * ASTRD + pcol(key)] = f2tf(vv_[e]);      // V^T: [d][key']
            }
        }
        __syncthreads();

        // ---- S = Q @ K^T (n = keys, k = d) ----
        float s[8][4];
#pragma unroll
        for (int nt = 0; nt < 8; nt++)
#pragma unroll
            for (int r = 0; r < 4; r++) s[nt][r] = 0.0f;

#pragma unroll
        for (int ks = 0; ks < 8; ks++) {
            uint2 alo = *(const uint2*)&Qs[r0 * ASTRD + ks * 8 + 2 * t];
            uint2 ahi = *(const uint2*)&Qs[(r0 + 8) * ASTRD + ks * 8 + 2 * t];
            uint32_t a[4] = {alo.x, ahi.x, alo.y, ahi.y};
#pragma unroll
            for (int nt = 0; nt < 8; nt++) {
                uint2 bb = *(const uint2*)&Ks[(nt * 8 + g) * ASTRD + ks * 8 + 2 * t];
                uint32_t bf2[2] = {bb.x, bb.y};
                mma_tf32(s[nt], a, bf2);
            }
        }

        // ---- online softmax (rows g and g+8; quad = same row) ----
        float mx0 = -CUDART_INF_F, mx1 = -CUDART_INF_F;
#pragma unroll
        for (int nt = 0; nt < 8; nt++) {
            mx0 = fmaxf(mx0, fmaxf(s[nt][0], s[nt][1]));
            mx1 = fmaxf(mx1, fmaxf(s[nt][2], s[nt][3]));
        }
        mx0 = fmaxf(mx0, __shfl_xor_sync(0xffffffffu, mx0, 1));
        mx0 = fmaxf(mx0, __shfl_xor_sync(0xffffffffu, mx0, 2));
        mx1 = fmaxf(mx1, __shfl_xor_sync(0xffffffffu, mx1, 1));
        mx1 = fmaxf(mx1, __shfl_xor_sync(0xffffffffu, mx1, 2));
        const float nm0 = fmaxf(m0, mx0), nm1 = fmaxf(m1, mx1);
        const float cr0 = __expf(m0 - nm0), cr1 = __expf(m1 - nm1);
        float rs0 = 0.0f, rs1 = 0.0f;
#pragma unroll
        for (int nt = 0; nt < 8; nt++) {
            s[nt][0] = __expf(s[nt][0] - nm0);
            s[nt][1] = __expf(s[nt][1] - nm0);
            s[nt][2] = __expf(s[nt][2] - nm1);
            s[nt][3] = __expf(s[nt][3] - nm1);
            rs0 += s[nt][0] + s[nt][1];
            rs1 += s[nt][2] + s[nt][3];
        }
        rs0 += __shfl_xor_sync(0xffffffffu, rs0, 1);
        rs0 += __shfl_xor_sync(0xffffffffu, rs0, 2);
        rs1 += __shfl_xor_sync(0xffffffffu, rs1, 1);
        rs1 += __shfl_xor_sync(0xffffffffu, rs1, 2);
        l0 = l0 * cr0 + rs0;  m0 = nm0;
        l1 = l1 * cr1 + rs1;  m1 = nm1;
#pragma unroll
        for (int nt = 0; nt < 8; nt++) {
            o[nt][0] *= cr0; o[nt][1] *= cr0;
            o[nt][2] *= cr1; o[nt][3] *= cr1;
        }

        // ---- P: C-frag -> smem (per-warp private rows) ----
#pragma unroll
        for (int nt = 0; nt < 8; nt++) {
            const int j0 = nt * 8 + 2 * t;
            Ps[r0 * ASTRD + pcol(j0)]           = f2tf(s[nt][0]);
            Ps[r0 * ASTRD + pcol(j0 + 1)]       = f2tf(s[nt][1]);
            Ps[(r0 + 8) * ASTRD + pcol(j0)]     = f2tf(s[nt][2]);
            Ps[(r0 + 8) * ASTRD + pcol(j0 + 1)] = f2tf(s[nt][3]);
        }
        __syncwarp();

        // ---- O += P @ V (n = d, k = keys) ----
#pragma unroll
        for (int ks = 0; ks < 8; ks++) {
            uint2 plo = *(const uint2*)&Ps[r0 * ASTRD + ks * 8 + 2 * t];
            uint2 phi = *(const uint2*)&Ps[(r0 + 8) * ASTRD + ks * 8 + 2 * t];
            uint32_t a[4] = {plo.x, phi.x, plo.y, phi.y};
#pragma unroll
            for (int nt = 0; nt < 8; nt++) {
                uint2 bb = *(const uint2*)&Vs[(nt * 8 + g) * ASTRD + ks * 8 + 2 * t];
                uint32_t bf2[2] = {bb.x, bb.y};
                mma_tf32(o[nt], a, bf2);
            }
        }
        __syncwarp();
    }

    // ---- epilogue: normalize, store to [B*N, 768] ----
    const float inv0 = 1.0f / l0, inv1 = 1.0f / l1;
    const int grow = b * NN + q0 + 16 * w + g;
    float* or0 = outp + (size_t)grow * DIMC + h * HD;
    float* or1 = outp + (size_t)(grow + 8) * DIMC + h * HD;
#pragma unroll
    for (int nt = 0; nt < 8; nt++) {
        const int col = nt * 8 + 2 * t;
        float2 v0; v0.x = o[nt][0] * inv0; v0.y = o[nt][1] * inv0;
        float2 v1; v1.x = o[nt][2] * inv1; v1.y = o[nt][3] * inv1;
        *(float2*)(or0 + col) = v0;
        *(float2*)(or1 + col) = v1;
    }
}

// ---------------------------------------------------------------------------
extern "C" void kernel_launch(void* const* d_in, const int* in_sizes, int n_in,
                              void* d_out, int out_size)
{
    const float* x      = (const float*)d_in[0];
    const float* w_qkv  = (const float*)d_in[1];
    const float* b_qkv  = (const float*)d_in[2];
    const float* w_proj = (const float*)d_in[3];
    const float* b_proj = (const float*)d_in[4];
    float* out = (float*)d_out;

    float *qkv_s = nullptr, *att_s = nullptr;
    cudaGetSymbolAddress((void**)&qkv_s, g_qkv);
    cudaGetSymbolAddress((void**)&att_s, g_att);

    cudaFuncSetAttribute(gemm_mma, cudaFuncAttributeMaxDynamicSharedMemorySize, GEMM_SMEM);
    cudaFuncSetAttribute(attn_mma, cudaFuncAttributeMaxDynamicSharedMemorySize, ATT_SMEM);

    // 1) QKV GEMM: [8192,768] @ [768,2304] + bias
    {
        dim3 grid((3 * DIMC) / 128, MTOK / 128);
        gemm_mma<<<grid, 256, GEMM_SMEM>>>(x, w_qkv, b_qkv, qkv_s, 3 * DIMC, DIMC);
    }

    // 2) Flash attention (tf32 mma): 4*12*16 = 768 blocks
    attn_mma<<<BB * HEADS * 16, 256, ATT_SMEM>>>(qkv_s, att_s);

    // 3) Projection GEMM: [8192,768] @ [768,768] + bias
    {
        dim3 grid(DIMC / 128, MTOK / 128);
        gemm_mma<<<grid, 256, GEMM_SMEM>>>(att_s, w_proj, b_proj, out, DIMC, DIMC);
    }
}